// round 1
// baseline (speedup 1.0000x reference)
#include <cuda_runtime.h>
#include <cstdint>

#define NN    50000
#define NE    500000
#define DIM   160
#define HEADS 5
#define MH    50
#define NV4   (DIM/4)      // 40 float4 per row
#define TILE  64
#define NCHUNK ((NN + 31) / 32)

// ---------------- scratch (static device globals: allocation-free) ----------
__device__ float    g_xl[NN * DIM];
__device__ float    g_xr[NN * DIM];
__device__ float    g_attn[NN * DIM];
__device__ float    g_sexp[(size_t)NE * HEADS];
__device__ unsigned g_smax[NN * HEADS];
__device__ float    g_ssum[NN * HEADS];

// ordered-uint mapping for float atomicMax
__device__ __forceinline__ unsigned f2u(float f) {
    unsigned u = __float_as_uint(f);
    return (u >> 31) ? ~u : (u | 0x80000000u);
}
__device__ __forceinline__ float u2f(unsigned u) {
    return __uint_as_float((u >> 31) ? (u & 0x7fffffffu) : ~u);
}

__device__ __forceinline__ float selu_f(float v) {
    const float sc = 1.0507009873554805f, al = 1.6732632423543772f;
    return v > 0.f ? sc * v : sc * al * (expf(v) - 1.f);
}

// ---------------- zero scratch ----------------
__global__ void zero_kernel() {
    int i = blockIdx.x * blockDim.x + threadIdx.x;
    if (i < NN * DIM / 4) ((float4*)g_attn)[i] = make_float4(0.f, 0.f, 0.f, 0.f);
    if (i < NN * HEADS) { g_smax[i] = 0u; g_ssum[i] = 0.f; }
}

// ---------------- cp.async tile loader: 64 rows x 160 floats ----------------
__device__ __forceinline__ void tile_load_async(float* buf, const float* src_mat,
                                                long row0, long nrows, int tid) {
    unsigned base = (unsigned)__cvta_generic_to_shared(buf);
    #pragma unroll
    for (int it = 0; it < 10; it++) {
        int i = tid + it * 256;                // 2560 float4 total
        int r = i / NV4;
        long row = row0 + r;
        const float4* p = (const float4*)src_mat +
                          (row < nrows ? row * NV4 + (i - r * NV4) : 0);
        int sz = (row < nrows) ? 16 : 0;
        asm volatile("cp.async.cg.shared.global [%0], [%1], 16, %2;\n"
                     :: "r"(base + (unsigned)i * 16u), "l"(p), "r"(sz));
    }
}

// ---------------- shared GEMM mainloop: 64 rows x 160 cols, K=160 -----------
__device__ __forceinline__ void gemm_tile(const float* __restrict__ W_s,
                                          const float* __restrict__ a_s,
                                          int warp, int lane, float acc[8][5]) {
    #pragma unroll
    for (int r = 0; r < 8; r++)
        #pragma unroll
        for (int c = 0; c < 5; c++) acc[r][c] = 0.f;
    #pragma unroll 2
    for (int k = 0; k < DIM; k += 4) {
        float4 xv[8];
        #pragma unroll
        for (int r = 0; r < 8; r++)
            xv[r] = *(const float4*)(a_s + (warp * 8 + r) * DIM + k);
        #pragma unroll
        for (int kk = 0; kk < 4; kk++) {
            float wv[5];
            #pragma unroll
            for (int c = 0; c < 5; c++) wv[c] = W_s[(k + kk) * DIM + lane + 32 * c];
            #pragma unroll
            for (int r = 0; r < 8; r++) {
                float xs = (&xv[r].x)[kk];
                #pragma unroll
                for (int c = 0; c < 5; c++) acc[r][c] = fmaf(xs, wv[c], acc[r][c]);
            }
        }
    }
}

// ---------------- K1: xl = x@Wl+bl, xr = x@Wr+br (grid.y selects) -----------
__global__ __launch_bounds__(256, 1)
void node_transform_kernel(const float* __restrict__ x,
                           const float* __restrict__ Wl, const float* __restrict__ bl,
                           const float* __restrict__ Wr, const float* __restrict__ br) {
    extern __shared__ float sm[];
    float* W_s  = sm;                  // 160*160
    float* buf0 = sm + DIM * DIM;      // 64*160
    float* buf1 = buf0 + TILE * DIM;   // 64*160
    const float* W    = blockIdx.y ? Wr : Wl;
    const float* bias = blockIdx.y ? br : bl;
    float* out        = blockIdx.y ? g_xr : g_xl;
    int tid = threadIdx.x, lane = tid & 31, warp = tid >> 5;

    for (int i = tid; i < DIM * DIM / 4; i += 256)
        ((float4*)W_s)[i] = ((const float4*)W)[i];
    float bv[5];
    #pragma unroll
    for (int c = 0; c < 5; c++) bv[c] = bias[lane + 32 * c];

    int ntiles = (NN + TILE - 1) / TILE;
    float* cur = buf0; float* nxt = buf1;
    tile_load_async(cur, x, (long)blockIdx.x * TILE, NN, tid);
    asm volatile("cp.async.commit_group;\n");
    for (int t = blockIdx.x; t < ntiles; t += gridDim.x) {
        tile_load_async(nxt, x, (long)(t + gridDim.x) * TILE, NN, tid);
        asm volatile("cp.async.commit_group;\n");
        asm volatile("cp.async.wait_group 1;\n");
        __syncthreads();
        float acc[8][5];
        gemm_tile(W_s, cur, warp, lane, acc);
        long r0 = (long)t * TILE + warp * 8;
        #pragma unroll
        for (int r = 0; r < 8; r++) {
            long gr = r0 + r;
            if (gr < NN) {
                #pragma unroll
                for (int c = 0; c < 5; c++)
                    out[gr * DIM + lane + 32 * c] = acc[r][c] + bv[c];
            }
        }
        __syncthreads();
        float* tmp = cur; cur = nxt; nxt = tmp;
    }
}

// ---------------- K2: ea = edge_attr@We, fused gather + score + segmax ------
__global__ __launch_bounds__(256, 1)
void edge_score_kernel(const float* __restrict__ edge_attr,
                       const int* __restrict__ src, const int* __restrict__ dst,
                       const float* __restrict__ We, const float* __restrict__ att) {
    extern __shared__ float sm[];
    float* W_s   = sm;
    float* buf0  = sm + DIM * DIM;
    float* buf1  = buf0 + TILE * DIM;
    float* att_s = buf1 + TILE * DIM;
    int tid = threadIdx.x, lane = tid & 31, warp = tid >> 5;

    for (int i = tid; i < DIM * DIM / 4; i += 256)
        ((float4*)W_s)[i] = ((const float4*)We)[i];
    if (tid < DIM) att_s[tid] = att[tid];

    int ntiles = (NE + TILE - 1) / TILE;
    float* cur = buf0; float* nxt = buf1;
    tile_load_async(cur, edge_attr, (long)blockIdx.x * TILE, NE, tid);
    asm volatile("cp.async.commit_group;\n");
    for (int t = blockIdx.x; t < ntiles; t += gridDim.x) {
        tile_load_async(nxt, edge_attr, (long)(t + gridDim.x) * TILE, NE, tid);
        asm volatile("cp.async.commit_group;\n");
        asm volatile("cp.async.wait_group 1;\n");
        __syncthreads();
        float acc[8][5];
        gemm_tile(W_s, cur, warp, lane, acc);
        int e0 = t * TILE + warp * 8;
        #pragma unroll
        for (int r = 0; r < 8; r++) {
            int e = e0 + r;
            if (e < NE) {                      // uniform across warp
                int s = src[e], d = dst[e];
                const float* xlr = g_xl + (long)s * DIM;
                const float* xrr = g_xr + (long)d * DIM;
                #pragma unroll
                for (int c = 0; c < 5; c++) {  // c == head, lane == channel
                    int col = lane + 32 * c;
                    float m = acc[r][c] + xlr[col] + xrr[col];
                    m = (m > 0.f) ? m : 0.2f * m;         // leaky_relu 0.2
                    float v = m * att_s[col];
                    #pragma unroll
                    for (int off = 16; off; off >>= 1)
                        v += __shfl_xor_sync(0xffffffffu, v, off);
                    if (lane == 0) {
                        g_sexp[(long)e * HEADS + c] = v;  // raw score for now
                        atomicMax(&g_smax[d * HEADS + c], f2u(v));
                    }
                }
            }
        }
        __syncthreads();
        float* tmp = cur; cur = nxt; nxt = tmp;
    }
}

// ---------------- K3: sexp = exp(score - smax[dst]); ssum += sexp -----------
__global__ void expsum_kernel(const int* __restrict__ dst) {
    long i = (long)blockIdx.x * blockDim.x + threadIdx.x;
    if (i >= (long)NE * HEADS) return;
    int e = (int)(i / HEADS);
    int h = (int)(i - (long)e * HEADS);
    int d = dst[e];
    float mx = u2f(g_smax[d * HEADS + h]);
    float se = expf(g_sexp[i] - mx);
    g_sexp[i] = se;
    atomicAdd(&g_ssum[d * HEADS + h], se);
}

// ---------------- K4: attn[dst] += alpha * xl[src] (warp per edge) ----------
__global__ __launch_bounds__(256)
void scatter_kernel(const int* __restrict__ src, const int* __restrict__ dst) {
    int gw = (int)(((long)blockIdx.x * blockDim.x + threadIdx.x) >> 5);
    int lane = threadIdx.x & 31;
    if (gw >= NE) return;
    int s = src[gw], d = dst[gw];
    float a = 0.f;
    if (lane < HEADS)
        a = g_sexp[(long)gw * HEADS + lane] / g_ssum[d * HEADS + lane];
    const float* xlr = g_xl + (long)s * DIM;
    float* ar = g_attn + (long)d * DIM;
    #pragma unroll
    for (int c = 0; c < 5; c++) {
        float alpha = __shfl_sync(0xffffffffu, a, c);
        atomicAdd(&ar[lane + 32 * c], alpha * xlr[lane + 32 * c]);
    }
}

// ---------------- K5: fused tail: LN1 -> MLP(160->50->160) -> LN2 -----------
__global__ __launch_bounds__(256, 2)
void tail_kernel(const float* __restrict__ x, const float* __restrict__ bias,
                 const float* __restrict__ g1, const float* __restrict__ bt1,
                 const float* __restrict__ W1, const float* __restrict__ b1,
                 const float* __restrict__ gm, const float* __restrict__ bm,
                 const float* __restrict__ W2, const float* __restrict__ b2,
                 const float* __restrict__ g2, const float* __restrict__ bt2,
                 float* __restrict__ out) {
    extern __shared__ float sm[];
    float* W1_s  = sm;                 // 160*50
    float* W2_s  = W1_s + DIM * MH;    // 50*160
    float* hbuf  = W2_s + MH * DIM;    // 32*161 (pad for bank-free row access)
    float* tbuf  = hbuf + 32 * 161;    // 32*51
    float* bias_s = tbuf + 32 * 51;
    float* g1_s  = bias_s + DIM;
    float* bt1_s = g1_s + DIM;
    float* b2_s  = bt1_s + DIM;
    float* g2_s  = b2_s + DIM;
    float* bt2_s = g2_s + DIM;
    float* b1_s  = bt2_s + DIM;
    float* gm_s  = b1_s + MH;
    float* bm_s  = gm_s + MH;
    int tid = threadIdx.x, lane = tid & 31, warp = tid >> 5;

    for (int i = tid; i < DIM * MH; i += 256) { W1_s[i] = W1[i]; W2_s[i] = W2[i]; }
    if (tid < DIM) {
        bias_s[tid] = bias[tid]; g1_s[tid] = g1[tid]; bt1_s[tid] = bt1[tid];
        b2_s[tid] = b2[tid]; g2_s[tid] = g2[tid]; bt2_s[tid] = bt2[tid];
    }
    if (tid < MH) { b1_s[tid] = b1[tid]; gm_s[tid] = gm[tid]; bm_s[tid] = bm[tid]; }
    __syncthreads();

    for (int chunk = blockIdx.x; chunk < NCHUNK; chunk += gridDim.x) {
        int n0 = chunk * 32;
        // --- phase A: h = LN(x + attn + bias) -> hbuf (warp per node) ---
        #pragma unroll
        for (int i = 0; i < 4; i++) {
            int nl = warp + 8 * i;
            long n = n0 + nl;
            float v[5];
            if (n < NN) {
                #pragma unroll
                for (int c = 0; c < 5; c++) {
                    int col = lane + 32 * c;
                    v[c] = x[n * DIM + col] + g_attn[n * DIM + col] + bias_s[col];
                }
            } else {
                #pragma unroll
                for (int c = 0; c < 5; c++) v[c] = 0.f;
            }
            float s1 = 0.f, s2 = 0.f;
            #pragma unroll
            for (int c = 0; c < 5; c++) { s1 += v[c]; s2 += v[c] * v[c]; }
            #pragma unroll
            for (int off = 16; off; off >>= 1) {
                s1 += __shfl_xor_sync(0xffffffffu, s1, off);
                s2 += __shfl_xor_sync(0xffffffffu, s2, off);
            }
            float mu = s1 * (1.f / DIM);
            float rstd = rsqrtf(s2 * (1.f / DIM) - mu * mu + 1e-5f);
            #pragma unroll
            for (int c = 0; c < 5; c++) {
                int col = lane + 32 * c;
                hbuf[nl * 161 + col] = (v[c] - mu) * rstd * g1_s[col] + bt1_s[col];
            }
        }
        __syncthreads();
        // --- phase B: t = selu(h@W1 + b1) -> tbuf (4 nodes x 2 cols / thread)
        {
            int cg = lane, ng = warp;
            float a0[4] = {0.f,0.f,0.f,0.f}, a1[4] = {0.f,0.f,0.f,0.f};
            for (int k = 0; k < DIM; k++) {
                float w0 = W1_s[k * MH + cg];
                float w1 = (cg < MH - 32) ? W1_s[k * MH + cg + 32] : 0.f;
                #pragma unroll
                for (int i = 0; i < 4; i++) {
                    float hv = hbuf[(ng * 4 + i) * 161 + k];
                    a0[i] = fmaf(hv, w0, a0[i]);
                    a1[i] = fmaf(hv, w1, a1[i]);
                }
            }
            #pragma unroll
            for (int i = 0; i < 4; i++) {
                int nl = ng * 4 + i;
                tbuf[nl * 51 + cg] = selu_f(a0[i] + b1_s[cg]);
                if (cg < MH - 32)
                    tbuf[nl * 51 + cg + 32] = selu_f(a1[i] + b1_s[cg + 32]);
            }
        }
        __syncthreads();
        // --- LN over 50 (thread per node, conflict-free via stride 51) ---
        if (tid < 32) {
            float s1 = 0.f, s2 = 0.f;
            for (int k = 0; k < MH; k++) { float t = tbuf[tid * 51 + k]; s1 += t; s2 += t * t; }
            float mu = s1 * (1.f / MH);
            float rstd = rsqrtf(s2 * (1.f / MH) - mu * mu + 1e-5f);
            for (int k = 0; k < MH; k++)
                tbuf[tid * 51 + k] = (tbuf[tid * 51 + k] - mu) * rstd * gm_s[k] + bm_s[k];
        }
        __syncthreads();
        // --- phase C: mlp = u@W2 + b2; out = LN(h + mlp) (warp = 4 nodes) ---
        {
            float acc[4][5];
            #pragma unroll
            for (int i = 0; i < 4; i++)
                #pragma unroll
                for (int c = 0; c < 5; c++) acc[i][c] = 0.f;
            for (int k = 0; k < MH; k++) {
                float wv[5];
                #pragma unroll
                for (int c = 0; c < 5; c++) wv[c] = W2_s[k * DIM + lane + 32 * c];
                #pragma unroll
                for (int i = 0; i < 4; i++) {
                    float uv = tbuf[(warp * 4 + i) * 51 + k];
                    #pragma unroll
                    for (int c = 0; c < 5; c++) acc[i][c] = fmaf(uv, wv[c], acc[i][c]);
                }
            }
            #pragma unroll
            for (int i = 0; i < 4; i++) {
                int nl = warp * 4 + i;
                long n = n0 + nl;
                float v[5];
                #pragma unroll
                for (int c = 0; c < 5; c++) {
                    int col = lane + 32 * c;
                    v[c] = hbuf[nl * 161 + col] + acc[i][c] + b2_s[col];
                }
                float s1 = 0.f, s2 = 0.f;
                #pragma unroll
                for (int c = 0; c < 5; c++) { s1 += v[c]; s2 += v[c] * v[c]; }
                #pragma unroll
                for (int off = 16; off; off >>= 1) {
                    s1 += __shfl_xor_sync(0xffffffffu, s1, off);
                    s2 += __shfl_xor_sync(0xffffffffu, s2, off);
                }
                float mu = s1 * (1.f / DIM);
                float rstd = rsqrtf(s2 * (1.f / DIM) - mu * mu + 1e-5f);
                if (n < NN) {
                    #pragma unroll
                    for (int c = 0; c < 5; c++) {
                        int col = lane + 32 * c;
                        out[n * DIM + col] = (v[c] - mu) * rstd * g2_s[col] + bt2_s[col];
                    }
                }
            }
        }
        __syncthreads();
    }
}

// ---------------- launch ----------------
extern "C" void kernel_launch(void* const* d_in, const int* in_sizes, int n_in,
                              void* d_out, int out_size) {
    const float* x         = (const float*)d_in[0];
    const int*   edge_index= (const int*)d_in[1];
    const float* edge_attr = (const float*)d_in[2];
    // d_in[3] = u, d_in[4] = batch (unused by reference)
    const float* Wl  = (const float*)d_in[5];
    const float* bl  = (const float*)d_in[6];
    const float* Wr  = (const float*)d_in[7];
    const float* br  = (const float*)d_in[8];
    const float* We  = (const float*)d_in[9];
    const float* att = (const float*)d_in[10];
    const float* bias= (const float*)d_in[11];
    const float* g1  = (const float*)d_in[12];
    const float* bt1 = (const float*)d_in[13];
    const float* W1  = (const float*)d_in[14];
    const float* b1  = (const float*)d_in[15];
    const float* gm  = (const float*)d_in[16];
    const float* bm  = (const float*)d_in[17];
    const float* W2  = (const float*)d_in[18];
    const float* b2  = (const float*)d_in[19];
    const float* g2  = (const float*)d_in[20];
    const float* bt2 = (const float*)d_in[21];
    float* out = (float*)d_out;
    const int* src = edge_index;
    const int* dst = edge_index + NE;

    const int SM_NODE = (DIM * DIM + 2 * TILE * DIM) * (int)sizeof(float);          // 143360
    const int SM_EDGE = (DIM * DIM + 2 * TILE * DIM + DIM) * (int)sizeof(float);    // 144000
    const int SM_TAIL = (2 * DIM * MH + 32 * 161 + 32 * 51 + 6 * DIM + 3 * MH)
                        * (int)sizeof(float);                                       // 95576
    cudaFuncSetAttribute(node_transform_kernel, cudaFuncAttributeMaxDynamicSharedMemorySize, SM_NODE);
    cudaFuncSetAttribute(edge_score_kernel,     cudaFuncAttributeMaxDynamicSharedMemorySize, SM_EDGE);
    cudaFuncSetAttribute(tail_kernel,           cudaFuncAttributeMaxDynamicSharedMemorySize, SM_TAIL);

    zero_kernel<<<(NN * DIM / 4 + 255) / 256, 256>>>();
    node_transform_kernel<<<dim3(148, 2), 256, SM_NODE>>>(x, Wl, bl, Wr, br);
    edge_score_kernel<<<148, 256, SM_EDGE>>>(edge_attr, src, dst, We, att);
    expsum_kernel<<<((long)NE * HEADS + 255) / 256, 256>>>(dst);
    scatter_kernel<<<(NE * 32 + 255) / 256, 256>>>(src, dst);
    tail_kernel<<<296, 256, SM_TAIL>>>(x, bias, g1, bt1, W1, b1, gm, bm,
                                       W2, b2, g2, bt2, out);
}

// round 2
// speedup vs baseline: 1.1078x; 1.1078x over previous
#include <cuda_runtime.h>
#include <cstdint>

typedef unsigned long long ull;

#define NN    50000
#define NE    500000
#define DIM   160
#define HEADS 5
#define MH    50
#define NV4   (DIM/4)      // 40 float4 per row
#define TILE  64
#define WTS   162          // padded stride for transposed W (bank/align friendly)
#define NB    ((NN + 255) / 256)   // 196 scan blocks
#define NCHUNK ((NN + 31) / 32)

// ---------------- scratch (static device globals: allocation-free) ----------
__device__ float g_xl[NN * DIM];
__device__ float g_xr[NN * DIM];
__device__ float g_attn[NN * DIM];
__device__ float g_alpha[(size_t)NE * HEADS];
__device__ int   g_deg[NN];
__device__ int   g_off[NN];
__device__ int   g_cur[NN];
__device__ int   g_eid[NE];
__device__ int   g_bsum[256];

__device__ __forceinline__ float selu_f(float v) {
    const float sc = 1.0507009873554805f, al = 1.6732632423543772f;
    return v > 0.f ? sc * v : sc * al * (expf(v) - 1.f);
}

#define FFMA2(d, a, b) asm("fma.rn.f32x2 %0, %1, %2, %0;" : "+l"(d) : "l"(a), "l"(b))

__device__ __forceinline__ float unpack_add(ull v) {
    return __uint_as_float((unsigned)v) + __uint_as_float((unsigned)(v >> 32));
}

// ---------------- CSR build ----------------
__global__ void zero_deg_kernel() {
    int i = blockIdx.x * blockDim.x + threadIdx.x;
    if (i < NN) g_deg[i] = 0;
}
__global__ void count_kernel(const int* __restrict__ dst) {
    int e = blockIdx.x * blockDim.x + threadIdx.x;
    if (e < NE) atomicAdd(&g_deg[dst[e]], 1);
}
__global__ void scan1_kernel() {
    __shared__ int wsum[8];
    int tid = threadIdx.x, lane = tid & 31, warp = tid >> 5;
    int i = blockIdx.x * 256 + tid;
    int v = (i < NN) ? g_deg[i] : 0;
    int x = v;
    #pragma unroll
    for (int d = 1; d < 32; d <<= 1) {
        int y = __shfl_up_sync(0xffffffffu, x, d);
        if (lane >= d) x += y;
    }
    if (lane == 31) wsum[warp] = x;
    __syncthreads();
    if (tid == 0) {
        int s = 0;
        #pragma unroll
        for (int j = 0; j < 8; j++) { int t = wsum[j]; wsum[j] = s; s += t; }
        g_bsum[blockIdx.x] = s;
    }
    __syncthreads();
    if (i < NN) g_off[i] = x - v + wsum[warp];
}
__global__ void scan2_kernel() {
    __shared__ int wsum[8];
    int tid = threadIdx.x, lane = tid & 31, warp = tid >> 5;
    int v = (tid < NB) ? g_bsum[tid] : 0;
    int x = v;
    #pragma unroll
    for (int d = 1; d < 32; d <<= 1) {
        int y = __shfl_up_sync(0xffffffffu, x, d);
        if (lane >= d) x += y;
    }
    if (lane == 31) wsum[warp] = x;
    __syncthreads();
    if (tid == 0) {
        int s = 0;
        #pragma unroll
        for (int j = 0; j < 8; j++) { int t = wsum[j]; wsum[j] = s; s += t; }
    }
    __syncthreads();
    if (tid < NB) g_bsum[tid] = x - v + wsum[warp];
}
__global__ void scan3_kernel() {
    int i = blockIdx.x * blockDim.x + threadIdx.x;
    if (i < NN) {
        int o = g_off[i] + g_bsum[i >> 8];
        g_off[i] = o;
        g_cur[i] = o;
    }
}
__global__ void fill_kernel(const int* __restrict__ dst) {
    int e = blockIdx.x * blockDim.x + threadIdx.x;
    if (e < NE) {
        int pos = atomicAdd(&g_cur[dst[e]], 1);
        g_eid[pos] = e;
    }
}

// ---------------- cp.async tile loader: 64 rows x 160 floats ----------------
__device__ __forceinline__ void tile_load_async(float* buf, const float* src_mat,
                                                long row0, long nrows, int tid) {
    unsigned base = (unsigned)__cvta_generic_to_shared(buf);
    #pragma unroll
    for (int it = 0; it < 10; it++) {
        int i = tid + it * 256;                // 2560 float4 total
        int r = i / NV4;
        long row = row0 + r;
        const float4* p = (const float4*)src_mat +
                          (row < nrows ? row * NV4 + (i - r * NV4) : 0);
        int sz = (row < nrows) ? 16 : 0;
        asm volatile("cp.async.cg.shared.global [%0], [%1], 16, %2;\n"
                     :: "r"(base + (unsigned)i * 16u), "l"(p), "r"(sz));
    }
}

// ------- f32x2 GEMM mainloop: 64 rows x 160 cols, K=160, W transposed -------
// acc[r][c] packs {sum over even k, sum over odd k}; final value = lo + hi.
__device__ __forceinline__ void gemm_tile_f2(const float* __restrict__ Wt,
                                             const float* __restrict__ a_s,
                                             int warp, int lane, ull acc[8][5]) {
    #pragma unroll
    for (int r = 0; r < 8; r++)
        #pragma unroll
        for (int c = 0; c < 5; c++) acc[r][c] = 0ull;
    const float* arow = a_s + warp * 8 * DIM;
    #pragma unroll 2
    for (int k = 0; k < DIM; k += 4) {
        ulonglong2 xv[8];
        #pragma unroll
        for (int r = 0; r < 8; r++)
            xv[r] = *(const ulonglong2*)(arow + r * DIM + k);
        #pragma unroll
        for (int p = 0; p < 2; p++) {
            ull wv[5];
            #pragma unroll
            for (int c = 0; c < 5; c++)
                wv[c] = *(const ull*)(Wt + (lane + 32 * c) * WTS + k + 2 * p);
            #pragma unroll
            for (int r = 0; r < 8; r++) {
                ull xa = p ? xv[r].y : xv[r].x;
                #pragma unroll
                for (int c = 0; c < 5; c++) FFMA2(acc[r][c], xa, wv[c]);
            }
        }
    }
}

// load W [k][col] row-major from global -> transposed Wt[col][k] (stride WTS)
__device__ __forceinline__ void load_W_transposed(float* Wt, const float* W, int tid) {
    for (int i = tid; i < DIM * DIM; i += 256) {
        int kk = i / DIM, cc = i - kk * DIM;
        Wt[cc * WTS + kk] = W[i];
    }
}

// ---------------- K1: xl = x@Wl+bl, xr = x@Wr+br (grid.y selects) -----------
__global__ __launch_bounds__(256, 1)
void node_transform_kernel(const float* __restrict__ x,
                           const float* __restrict__ Wl, const float* __restrict__ bl,
                           const float* __restrict__ Wr, const float* __restrict__ br) {
    extern __shared__ float sm[];
    float* Wt   = sm;                   // 160*162
    float* buf0 = sm + DIM * WTS;       // 64*160
    float* buf1 = buf0 + TILE * DIM;    // 64*160
    const float* W    = blockIdx.y ? Wr : Wl;
    const float* bias = blockIdx.y ? br : bl;
    float* out        = blockIdx.y ? g_xr : g_xl;
    int tid = threadIdx.x, lane = tid & 31, warp = tid >> 5;

    load_W_transposed(Wt, W, tid);
    float bv[5];
    #pragma unroll
    for (int c = 0; c < 5; c++) bv[c] = bias[lane + 32 * c];

    int ntiles = (NN + TILE - 1) / TILE;
    float* cur = buf0; float* nxt = buf1;
    tile_load_async(cur, x, (long)blockIdx.x * TILE, NN, tid);
    asm volatile("cp.async.commit_group;\n");
    for (int t = blockIdx.x; t < ntiles; t += gridDim.x) {
        tile_load_async(nxt, x, (long)(t + gridDim.x) * TILE, NN, tid);
        asm volatile("cp.async.commit_group;\n");
        asm volatile("cp.async.wait_group 1;\n");
        __syncthreads();
        ull acc[8][5];
        gemm_tile_f2(Wt, cur, warp, lane, acc);
        long r0 = (long)t * TILE + warp * 8;
        #pragma unroll
        for (int r = 0; r < 8; r++) {
            long gr = r0 + r;
            if (gr < NN) {
                #pragma unroll
                for (int c = 0; c < 5; c++)
                    out[gr * DIM + lane + 32 * c] = unpack_add(acc[r][c]) + bv[c];
            }
        }
        __syncthreads();
        float* tmp = cur; cur = nxt; nxt = tmp;
    }
}

// ---------------- K2: ea = edge_attr@We, fused gather + score ---------------
__global__ __launch_bounds__(256, 1)
void edge_score_kernel(const float* __restrict__ edge_attr,
                       const int* __restrict__ src, const int* __restrict__ dst,
                       const float* __restrict__ We, const float* __restrict__ att) {
    extern __shared__ float sm[];
    float* Wt    = sm;
    float* buf0  = sm + DIM * WTS;
    float* buf1  = buf0 + TILE * DIM;
    float* att_s = buf1 + TILE * DIM;
    int tid = threadIdx.x, lane = tid & 31, warp = tid >> 5;

    load_W_transposed(Wt, We, tid);
    if (tid < DIM) att_s[tid] = att[tid];

    int ntiles = (NE + TILE - 1) / TILE;
    float* cur = buf0; float* nxt = buf1;
    tile_load_async(cur, edge_attr, (long)blockIdx.x * TILE, NE, tid);
    asm volatile("cp.async.commit_group;\n");
    for (int t = blockIdx.x; t < ntiles; t += gridDim.x) {
        tile_load_async(nxt, edge_attr, (long)(t + gridDim.x) * TILE, NE, tid);
        asm volatile("cp.async.commit_group;\n");
        asm volatile("cp.async.wait_group 1;\n");
        __syncthreads();
        ull acc[8][5];
        gemm_tile_f2(Wt, cur, warp, lane, acc);
        int e0 = t * TILE + warp * 8;
        #pragma unroll
        for (int r = 0; r < 8; r++) {
            int e = e0 + r;
            if (e < NE) {                      // uniform across warp
                int s = src[e], d = dst[e];
                const float* xlr = g_xl + (long)s * DIM;
                const float* xrr = g_xr + (long)d * DIM;
                #pragma unroll
                for (int c = 0; c < 5; c++) {  // c == head, lane == channel
                    int col = lane + 32 * c;
                    float m = unpack_add(acc[r][c]) + xlr[col] + xrr[col];
                    m = (m > 0.f) ? m : 0.2f * m;         // leaky_relu 0.2
                    float v = m * att_s[col];
                    #pragma unroll
                    for (int off = 16; off; off >>= 1)
                        v += __shfl_xor_sync(0xffffffffu, v, off);
                    if (lane == 0)
                        g_alpha[(long)e * HEADS + c] = v;  // raw score
                }
            }
        }
        __syncthreads();
        float* tmp = cur; cur = nxt; nxt = tmp;
    }
}

// ---------------- K3: per-node softmax over CSR (warp per node) -------------
__global__ __launch_bounds__(256)
void softmax_kernel() {
    int w = (int)(((long)blockIdx.x * blockDim.x + threadIdx.x) >> 5);
    int lane = threadIdx.x & 31;
    if (w >= NN) return;
    int off = g_off[w], deg = g_deg[w];
    if (deg == 0) return;
    float mx[5];
    #pragma unroll
    for (int h = 0; h < 5; h++) mx[h] = -3.4e38f;
    for (int i = lane; i < deg; i += 32) {
        long e = g_eid[off + i];
        #pragma unroll
        for (int h = 0; h < 5; h++) mx[h] = fmaxf(mx[h], g_alpha[e * 5 + h]);
    }
    #pragma unroll
    for (int h = 0; h < 5; h++)
        #pragma unroll
        for (int o = 16; o; o >>= 1)
            mx[h] = fmaxf(mx[h], __shfl_xor_sync(0xffffffffu, mx[h], o));
    float sm[5] = {0.f, 0.f, 0.f, 0.f, 0.f};
    for (int i = lane; i < deg; i += 32) {
        long e = g_eid[off + i];
        #pragma unroll
        for (int h = 0; h < 5; h++) {
            float v = expf(g_alpha[e * 5 + h] - mx[h]);
            g_alpha[e * 5 + h] = v;
            sm[h] += v;
        }
    }
    #pragma unroll
    for (int h = 0; h < 5; h++)
        #pragma unroll
        for (int o = 16; o; o >>= 1)
            sm[h] += __shfl_xor_sync(0xffffffffu, sm[h], o);
    float inv[5];
    #pragma unroll
    for (int h = 0; h < 5; h++) inv[h] = 1.f / sm[h];
    for (int i = lane; i < deg; i += 32) {
        long e = g_eid[off + i];
        #pragma unroll
        for (int h = 0; h < 5; h++) g_alpha[e * 5 + h] *= inv[h];
    }
}

// ---------------- K4: attn[n] = sum_e alpha * xl[src[e]] (warp per node) ----
__global__ __launch_bounds__(256)
void aggregate_kernel(const int* __restrict__ src) {
    int w = (int)(((long)blockIdx.x * blockDim.x + threadIdx.x) >> 5);
    int lane = threadIdx.x & 31;
    if (w >= NN) return;
    int off = g_off[w], deg = g_deg[w];
    float acc0 = 0.f, acc1 = 0.f, acc2 = 0.f, acc3 = 0.f, acc4 = 0.f;
    for (int base = 0; base < deg; base += 32) {
        int i = base + lane;
        int s = 0;
        float a0 = 0.f, a1 = 0.f, a2 = 0.f, a3 = 0.f, a4 = 0.f;
        if (i < deg) {
            long e = g_eid[off + i];
            s = src[e];
            const float* ap = g_alpha + e * 5;
            a0 = ap[0]; a1 = ap[1]; a2 = ap[2]; a3 = ap[3]; a4 = ap[4];
        }
        int m = min(32, deg - base);
        for (int j = 0; j < m; j++) {
            int ss = __shfl_sync(0xffffffffu, s, j);
            const float* xr = g_xl + (long)ss * DIM + lane;
            acc0 = fmaf(__shfl_sync(0xffffffffu, a0, j), xr[0],   acc0);
            acc1 = fmaf(__shfl_sync(0xffffffffu, a1, j), xr[32],  acc1);
            acc2 = fmaf(__shfl_sync(0xffffffffu, a2, j), xr[64],  acc2);
            acc3 = fmaf(__shfl_sync(0xffffffffu, a3, j), xr[96],  acc3);
            acc4 = fmaf(__shfl_sync(0xffffffffu, a4, j), xr[128], acc4);
        }
    }
    float* o = g_attn + (long)w * DIM + lane;
    o[0] = acc0; o[32] = acc1; o[64] = acc2; o[96] = acc3; o[128] = acc4;
}

// ---------------- K5: fused tail: LN1 -> MLP(160->50->160) -> LN2 -----------
__global__ __launch_bounds__(256, 2)
void tail_kernel(const float* __restrict__ x, const float* __restrict__ bias,
                 const float* __restrict__ g1, const float* __restrict__ bt1,
                 const float* __restrict__ W1, const float* __restrict__ b1,
                 const float* __restrict__ gm, const float* __restrict__ bm,
                 const float* __restrict__ W2, const float* __restrict__ b2,
                 const float* __restrict__ g2, const float* __restrict__ bt2,
                 float* __restrict__ out) {
    extern __shared__ float sm[];
    float* W1_s  = sm;                 // 160*50
    float* W2_s  = W1_s + DIM * MH;    // 50*160
    float* hbuf  = W2_s + MH * DIM;    // 32*161
    float* tbuf  = hbuf + 32 * 161;    // 32*51
    float* bias_s = tbuf + 32 * 51;
    float* g1_s  = bias_s + DIM;
    float* bt1_s = g1_s + DIM;
    float* b2_s  = bt1_s + DIM;
    float* g2_s  = b2_s + DIM;
    float* bt2_s = g2_s + DIM;
    float* b1_s  = bt2_s + DIM;
    float* gm_s  = b1_s + MH;
    float* bm_s  = gm_s + MH;
    int tid = threadIdx.x, lane = tid & 31, warp = tid >> 5;

    for (int i = tid; i < DIM * MH; i += 256) { W1_s[i] = W1[i]; W2_s[i] = W2[i]; }
    if (tid < DIM) {
        bias_s[tid] = bias[tid]; g1_s[tid] = g1[tid]; bt1_s[tid] = bt1[tid];
        b2_s[tid] = b2[tid]; g2_s[tid] = g2[tid]; bt2_s[tid] = bt2[tid];
    }
    if (tid < MH) { b1_s[tid] = b1[tid]; gm_s[tid] = gm[tid]; bm_s[tid] = bm[tid]; }
    __syncthreads();

    for (int chunk = blockIdx.x; chunk < NCHUNK; chunk += gridDim.x) {
        int n0 = chunk * 32;
        #pragma unroll
        for (int i = 0; i < 4; i++) {
            int nl = warp + 8 * i;
            long n = n0 + nl;
            float v[5];
            if (n < NN) {
                #pragma unroll
                for (int c = 0; c < 5; c++) {
                    int col = lane + 32 * c;
                    v[c] = x[n * DIM + col] + g_attn[n * DIM + col] + bias_s[col];
                }
            } else {
                #pragma unroll
                for (int c = 0; c < 5; c++) v[c] = 0.f;
            }
            float s1 = 0.f, s2 = 0.f;
            #pragma unroll
            for (int c = 0; c < 5; c++) { s1 += v[c]; s2 += v[c] * v[c]; }
            #pragma unroll
            for (int off = 16; off; off >>= 1) {
                s1 += __shfl_xor_sync(0xffffffffu, s1, off);
                s2 += __shfl_xor_sync(0xffffffffu, s2, off);
            }
            float mu = s1 * (1.f / DIM);
            float rstd = rsqrtf(s2 * (1.f / DIM) - mu * mu + 1e-5f);
            #pragma unroll
            for (int c = 0; c < 5; c++) {
                int col = lane + 32 * c;
                hbuf[nl * 161 + col] = (v[c] - mu) * rstd * g1_s[col] + bt1_s[col];
            }
        }
        __syncthreads();
        {
            int cg = lane, ng = warp;
            float a0[4] = {0.f,0.f,0.f,0.f}, a1[4] = {0.f,0.f,0.f,0.f};
            for (int k = 0; k < DIM; k++) {
                float w0 = W1_s[k * MH + cg];
                float w1 = (cg < MH - 32) ? W1_s[k * MH + cg + 32] : 0.f;
                #pragma unroll
                for (int i = 0; i < 4; i++) {
                    float hv = hbuf[(ng * 4 + i) * 161 + k];
                    a0[i] = fmaf(hv, w0, a0[i]);
                    a1[i] = fmaf(hv, w1, a1[i]);
                }
            }
            #pragma unroll
            for (int i = 0; i < 4; i++) {
                int nl = ng * 4 + i;
                tbuf[nl * 51 + cg] = selu_f(a0[i] + b1_s[cg]);
                if (cg < MH - 32)
                    tbuf[nl * 51 + cg + 32] = selu_f(a1[i] + b1_s[cg + 32]);
            }
        }
        __syncthreads();
        if (tid < 32) {
            float s1 = 0.f, s2 = 0.f;
            for (int k = 0; k < MH; k++) { float t = tbuf[tid * 51 + k]; s1 += t; s2 += t * t; }
            float mu = s1 * (1.f / MH);
            float rstd = rsqrtf(s2 * (1.f / MH) - mu * mu + 1e-5f);
            for (int k = 0; k < MH; k++)
                tbuf[tid * 51 + k] = (tbuf[tid * 51 + k] - mu) * rstd * gm_s[k] + bm_s[k];
        }
        __syncthreads();
        {
            float acc[4][5];
            #pragma unroll
            for (int i = 0; i < 4; i++)
                #pragma unroll
                for (int c = 0; c < 5; c++) acc[i][c] = 0.f;
            for (int k = 0; k < MH; k++) {
                float wv[5];
                #pragma unroll
                for (int c = 0; c < 5; c++) wv[c] = W2_s[k * DIM + lane + 32 * c];
                #pragma unroll
                for (int i = 0; i < 4; i++) {
                    float uv = tbuf[(warp * 4 + i) * 51 + k];
                    #pragma unroll
                    for (int c = 0; c < 5; c++) acc[i][c] = fmaf(uv, wv[c], acc[i][c]);
                }
            }
            #pragma unroll
            for (int i = 0; i < 4; i++) {
                int nl = warp * 4 + i;
                long n = n0 + nl;
                float v[5];
                #pragma unroll
                for (int c = 0; c < 5; c++) {
                    int col = lane + 32 * c;
                    v[c] = hbuf[nl * 161 + col] + acc[i][c] + b2_s[col];
                }
                float s1 = 0.f, s2 = 0.f;
                #pragma unroll
                for (int c = 0; c < 5; c++) { s1 += v[c]; s2 += v[c] * v[c]; }
                #pragma unroll
                for (int off = 16; off; off >>= 1) {
                    s1 += __shfl_xor_sync(0xffffffffu, s1, off);
                    s2 += __shfl_xor_sync(0xffffffffu, s2, off);
                }
                float mu = s1 * (1.f / DIM);
                float rstd = rsqrtf(s2 * (1.f / DIM) - mu * mu + 1e-5f);
                if (n < NN) {
                    #pragma unroll
                    for (int c = 0; c < 5; c++) {
                        int col = lane + 32 * c;
                        out[n * DIM + col] = (v[c] - mu) * rstd * g2_s[col] + bt2_s[col];
                    }
                }
            }
        }
        __syncthreads();
    }
}

// ---------------- launch ----------------
extern "C" void kernel_launch(void* const* d_in, const int* in_sizes, int n_in,
                              void* d_out, int out_size) {
    const float* x         = (const float*)d_in[0];
    const int*   edge_index= (const int*)d_in[1];
    const float* edge_attr = (const float*)d_in[2];
    const float* Wl  = (const float*)d_in[5];
    const float* bl  = (const float*)d_in[6];
    const float* Wr  = (const float*)d_in[7];
    const float* br  = (const float*)d_in[8];
    const float* We  = (const float*)d_in[9];
    const float* att = (const float*)d_in[10];
    const float* bias= (const float*)d_in[11];
    const float* g1  = (const float*)d_in[12];
    const float* bt1 = (const float*)d_in[13];
    const float* W1  = (const float*)d_in[14];
    const float* b1  = (const float*)d_in[15];
    const float* gm  = (const float*)d_in[16];
    const float* bm  = (const float*)d_in[17];
    const float* W2  = (const float*)d_in[18];
    const float* b2  = (const float*)d_in[19];
    const float* g2  = (const float*)d_in[20];
    const float* bt2 = (const float*)d_in[21];
    float* out = (float*)d_out;
    const int* src = edge_index;
    const int* dst = edge_index + NE;

    const int SM_NODE = (DIM * WTS + 2 * TILE * DIM) * (int)sizeof(float);
    const int SM_EDGE = (DIM * WTS + 2 * TILE * DIM + DIM) * (int)sizeof(float);
    const int SM_TAIL = (2 * DIM * MH + 32 * 161 + 32 * 51 + 6 * DIM + 3 * MH)
                        * (int)sizeof(float);
    cudaFuncSetAttribute(node_transform_kernel, cudaFuncAttributeMaxDynamicSharedMemorySize, SM_NODE);
    cudaFuncSetAttribute(edge_score_kernel,     cudaFuncAttributeMaxDynamicSharedMemorySize, SM_EDGE);
    cudaFuncSetAttribute(tail_kernel,           cudaFuncAttributeMaxDynamicSharedMemorySize, SM_TAIL);

    // CSR build
    zero_deg_kernel<<<(NN + 255) / 256, 256>>>();
    count_kernel<<<(NE + 255) / 256, 256>>>(dst);
    scan1_kernel<<<NB, 256>>>();
    scan2_kernel<<<1, 256>>>();
    scan3_kernel<<<(NN + 255) / 256, 256>>>();
    fill_kernel<<<(NE + 255) / 256, 256>>>(dst);
    // GEMMs + scores
    node_transform_kernel<<<dim3(148, 2), 256, SM_NODE>>>(x, Wl, bl, Wr, br);
    edge_score_kernel<<<148, 256, SM_EDGE>>>(edge_attr, src, dst, We, att);
    // softmax + aggregation (no atomics)
    softmax_kernel<<<(NN + 7) / 8, 256>>>();
    aggregate_kernel<<<(NN + 7) / 8, 256>>>(src);
    tail_kernel<<<296, 256, SM_TAIL>>>(x, bias, g1, bt1, W1, b1, gm, bm,
                                       W2, b2, g2, bt2, out);
}

// round 5
// speedup vs baseline: 1.4784x; 1.3346x over previous
#include <cuda_runtime.h>
#include <cstdint>

typedef unsigned long long ull;

#define NN    50000
#define NE    500000
#define DIM   160
#define HEADS 5
#define MH    50
#define NV4   (DIM/4)      // 40 float4 per row
#define TILE  96           // rows per GEMM tile
#define RPW   6            // rows per warp (16 warps)
#define WTS   162          // padded stride for transposed W
#define NB    ((NN + 255) / 256)   // scan blocks
#define NCHUNK ((NN + 31) / 32)

// ---------------- scratch (static device globals: allocation-free) ----------
__device__ float g_xl[NN * DIM];
__device__ float g_xr[NN * DIM];
__device__ float g_attn[NN * DIM];
__device__ float g_csc[(size_t)NE * HEADS];   // scores/alphas in CSR order
__device__ int   g_csrc[NE];                  // src node per CSR slot
__device__ int   g_pos[NE];                   // e -> CSR slot
__device__ int   g_deg[NN];
__device__ int   g_off[NN];
__device__ int   g_cur[NN];
__device__ int   g_bsum[256];

__device__ __forceinline__ float selu_f(float v) {
    const float sc = 1.0507009873554805f, al = 1.6732632423543772f;
    return v > 0.f ? sc * v : sc * al * (expf(v) - 1.f);
}

#define FFMA2(d, a, b) asm("fma.rn.f32x2 %0, %1, %2, %0;" : "+l"(d) : "l"(a), "l"(b))

__device__ __forceinline__ float unpack_add(ull v) {
    return __uint_as_float((unsigned)v) + __uint_as_float((unsigned)(v >> 32));
}

// ---------------- CSR build ----------------
__global__ void zero_deg_kernel() {
    int i = blockIdx.x * blockDim.x + threadIdx.x;
    if (i < NN) g_deg[i] = 0;
}
__global__ void count_kernel(const int* __restrict__ dst) {
    int e = blockIdx.x * blockDim.x + threadIdx.x;
    if (e < NE) atomicAdd(&g_deg[dst[e]], 1);
}
__global__ void scan1_kernel() {
    __shared__ int wsum[8];
    int tid = threadIdx.x, lane = tid & 31, warp = tid >> 5;
    int i = blockIdx.x * 256 + tid;
    int v = (i < NN) ? g_deg[i] : 0;
    int x = v;
    #pragma unroll
    for (int d = 1; d < 32; d <<= 1) {
        int y = __shfl_up_sync(0xffffffffu, x, d);
        if (lane >= d) x += y;
    }
    if (lane == 31) wsum[warp] = x;
    __syncthreads();
    if (tid == 0) {
        int s = 0;
        #pragma unroll
        for (int j = 0; j < 8; j++) { int t = wsum[j]; wsum[j] = s; s += t; }
        g_bsum[blockIdx.x] = s;
    }
    __syncthreads();
    if (i < NN) g_off[i] = x - v + wsum[warp];
}
__global__ void scan2_kernel() {
    __shared__ int wsum[8];
    int tid = threadIdx.x, lane = tid & 31, warp = tid >> 5;
    int v = (tid < NB) ? g_bsum[tid] : 0;
    int x = v;
    #pragma unroll
    for (int d = 1; d < 32; d <<= 1) {
        int y = __shfl_up_sync(0xffffffffu, x, d);
        if (lane >= d) x += y;
    }
    if (lane == 31) wsum[warp] = x;
    __syncthreads();
    if (tid == 0) {
        int s = 0;
        #pragma unroll
        for (int j = 0; j < 8; j++) { int t = wsum[j]; wsum[j] = s; s += t; }
    }
    __syncthreads();
    if (tid < NB) g_bsum[tid] = x - v + wsum[warp];
}
__global__ void scan3_kernel() {
    int i = blockIdx.x * blockDim.x + threadIdx.x;
    if (i < NN) {
        int o = g_off[i] + g_bsum[i >> 8];
        g_off[i] = o;
        g_cur[i] = o;
    }
}
__global__ void fill_kernel(const int* __restrict__ src, const int* __restrict__ dst) {
    int e = blockIdx.x * blockDim.x + threadIdx.x;
    if (e < NE) {
        int pos = atomicAdd(&g_cur[dst[e]], 1);
        g_pos[e] = pos;
        g_csrc[pos] = src[e];
    }
}

// ---------------- cp.async tile loader: 96 rows x 160 floats ----------------
__device__ __forceinline__ void tile_load_async(float* buf, const float* src_mat,
                                                long row0, long nrows, int tid) {
    unsigned base = (unsigned)__cvta_generic_to_shared(buf);
    #pragma unroll
    for (int it = 0; it < 8; it++) {
        int i = tid + it * 512;                // 3840 float4 total
        if (i < TILE * NV4) {
            int r = i / NV4;
            long row = row0 + r;
            const float4* p = (const float4*)src_mat +
                              (row < nrows ? row * NV4 + (i - r * NV4) : 0);
            int sz = (row < nrows) ? 16 : 0;
            asm volatile("cp.async.cg.shared.global [%0], [%1], 16, %2;\n"
                         :: "r"(base + (unsigned)i * 16u), "l"(p), "r"(sz));
        }
    }
}

// ------- f32x2 GEMM mainloop: 96 rows x 160 cols, K=160, W transposed -------
// acc[r][c] packs {even-k sum, odd-k sum}; final = lo + hi.
__device__ __forceinline__ void gemm_tile_f2(const float* __restrict__ Wt,
                                             const float* __restrict__ a_s,
                                             int warp, int lane, ull acc[RPW][5]) {
    #pragma unroll
    for (int r = 0; r < RPW; r++)
        #pragma unroll
        for (int c = 0; c < 5; c++) acc[r][c] = 0ull;
    const float* arow = a_s + warp * RPW * DIM;
    const float* wcol = Wt + lane * WTS;
    #pragma unroll 4
    for (int k = 0; k < DIM; k += 2) {
        ull xv[RPW];
        #pragma unroll
        for (int r = 0; r < RPW; r++)
            xv[r] = *(const ull*)(arow + r * DIM + k);   // warp-uniform: broadcast
        ull wv[5];
        #pragma unroll
        for (int c = 0; c < 5; c++)
            wv[c] = *(const ull*)(wcol + c * 32 * WTS + k);
        #pragma unroll
        for (int r = 0; r < RPW; r++)
            #pragma unroll
            for (int c = 0; c < 5; c++) FFMA2(acc[r][c], xv[r], wv[c]);
    }
}

// load W [k][col] row-major -> transposed Wt[col][k] (stride WTS)
__device__ __forceinline__ void load_W_transposed(float* Wt, const float* W, int tid) {
    for (int i = tid; i < DIM * DIM; i += 512) {
        int kk = i / DIM, cc = i - kk * DIM;
        Wt[cc * WTS + kk] = W[i];
    }
}

// ---------------- K: xl = x@Wl+bl, xr = x@Wr+br (grid.y selects) ------------
__global__ __launch_bounds__(512, 1)
void node_transform_kernel(const float* __restrict__ x,
                           const float* __restrict__ Wl, const float* __restrict__ bl,
                           const float* __restrict__ Wr, const float* __restrict__ br) {
    extern __shared__ float sm[];
    float* Wt   = sm;                   // 160*162
    float* buf0 = sm + DIM * WTS;       // 96*160
    float* buf1 = buf0 + TILE * DIM;    // 96*160
    const float* W    = blockIdx.y ? Wr : Wl;
    const float* bias = blockIdx.y ? br : bl;
    float* out        = blockIdx.y ? g_xr : g_xl;
    int tid = threadIdx.x, lane = tid & 31, warp = tid >> 5;

    load_W_transposed(Wt, W, tid);
    float bv[5];
    #pragma unroll
    for (int c = 0; c < 5; c++) bv[c] = bias[lane + 32 * c];

    int ntiles = (NN + TILE - 1) / TILE;
    float* cur = buf0; float* nxt = buf1;
    tile_load_async(cur, x, (long)blockIdx.x * TILE, NN, tid);
    asm volatile("cp.async.commit_group;\n");
    for (int t = blockIdx.x; t < ntiles; t += gridDim.x) {
        tile_load_async(nxt, x, (long)(t + gridDim.x) * TILE, NN, tid);
        asm volatile("cp.async.commit_group;\n");
        asm volatile("cp.async.wait_group 1;\n");
        __syncthreads();
        ull acc[RPW][5];
        gemm_tile_f2(Wt, cur, warp, lane, acc);
        long r0 = (long)t * TILE + warp * RPW;
        #pragma unroll
        for (int r = 0; r < RPW; r++) {
            long gr = r0 + r;
            if (gr < NN) {
                #pragma unroll
                for (int c = 0; c < 5; c++)
                    out[gr * DIM + lane + 32 * c] = unpack_add(acc[r][c]) + bv[c];
            }
        }
        __syncthreads();
        float* tmp = cur; cur = nxt; nxt = tmp;
    }
}

// ---------------- K: ea = edge_attr@We, fused gather + score (CSR out) ------
__global__ __launch_bounds__(512, 1)
void edge_score_kernel(const float* __restrict__ edge_attr,
                       const int* __restrict__ src, const int* __restrict__ dst,
                       const float* __restrict__ We, const float* __restrict__ att) {
    extern __shared__ float sm[];
    float* Wt    = sm;
    float* buf0  = sm + DIM * WTS;
    float* buf1  = buf0 + TILE * DIM;
    float* att_s = buf1 + TILE * DIM;
    int tid = threadIdx.x, lane = tid & 31, warp = tid >> 5;

    load_W_transposed(Wt, We, tid);
    if (tid < DIM) att_s[tid] = att[tid];

    int ntiles = (NE + TILE - 1) / TILE;
    float* cur = buf0; float* nxt = buf1;
    tile_load_async(cur, edge_attr, (long)blockIdx.x * TILE, NE, tid);
    asm volatile("cp.async.commit_group;\n");
    for (int t = blockIdx.x; t < ntiles; t += gridDim.x) {
        tile_load_async(nxt, edge_attr, (long)(t + gridDim.x) * TILE, NE, tid);
        asm volatile("cp.async.commit_group;\n");
        asm volatile("cp.async.wait_group 1;\n");
        __syncthreads();
        ull acc[RPW][5];
        gemm_tile_f2(Wt, cur, warp, lane, acc);
        int e0 = t * TILE + warp * RPW;
        #pragma unroll
        for (int r = 0; r < RPW; r++) {
            int e = e0 + r;
            if (e < NE) {                      // uniform across warp
                int s = src[e], d = dst[e], pos = g_pos[e];
                const float* xlr = g_xl + (long)s * DIM;
                const float* xrr = g_xr + (long)d * DIM;
                #pragma unroll
                for (int c = 0; c < 5; c++) {  // c == head, lane == channel
                    int col = lane + 32 * c;
                    float m = unpack_add(acc[r][c]) + xlr[col] + xrr[col];
                    m = (m > 0.f) ? m : 0.2f * m;         // leaky_relu 0.2
                    float v = m * att_s[col];
                    #pragma unroll
                    for (int off = 16; off; off >>= 1)
                        v += __shfl_xor_sync(0xffffffffu, v, off);
                    if (lane == 0)
                        g_csc[(long)pos * HEADS + c] = v;  // raw score, CSR slot
                }
            }
        }
        __syncthreads();
        float* tmp = cur; cur = nxt; nxt = tmp;
    }
}

// ---------------- per-node softmax over CSR (warp per node) -----------------
__global__ __launch_bounds__(256)
void softmax_kernel() {
    int w = (int)(((long)blockIdx.x * blockDim.x + threadIdx.x) >> 5);
    int lane = threadIdx.x & 31;
    if (w >= NN) return;
    long off = g_off[w]; int deg = g_deg[w];
    if (deg == 0) return;
    float mx[5];
    #pragma unroll
    for (int h = 0; h < 5; h++) mx[h] = -3.4e38f;
    for (int i = lane; i < deg; i += 32) {
        const float* p = g_csc + (off + i) * 5;
        #pragma unroll
        for (int h = 0; h < 5; h++) mx[h] = fmaxf(mx[h], p[h]);
    }
    #pragma unroll
    for (int h = 0; h < 5; h++)
        #pragma unroll
        for (int o = 16; o; o >>= 1)
            mx[h] = fmaxf(mx[h], __shfl_xor_sync(0xffffffffu, mx[h], o));
    float sm[5] = {0.f, 0.f, 0.f, 0.f, 0.f};
    for (int i = lane; i < deg; i += 32) {
        float* p = g_csc + (off + i) * 5;
        #pragma unroll
        for (int h = 0; h < 5; h++) {
            float v = expf(p[h] - mx[h]);
            p[h] = v;
            sm[h] += v;
        }
    }
    #pragma unroll
    for (int h = 0; h < 5; h++)
        #pragma unroll
        for (int o = 16; o; o >>= 1)
            sm[h] += __shfl_xor_sync(0xffffffffu, sm[h], o);
    float inv[5];
    #pragma unroll
    for (int h = 0; h < 5; h++) inv[h] = 1.f / sm[h];
    for (int i = lane; i < deg; i += 32) {
        float* p = g_csc + (off + i) * 5;
        #pragma unroll
        for (int h = 0; h < 5; h++) p[h] *= inv[h];
    }
}

// ------- attn[n] = sum_e alpha * xl[src[e]] (warp per node, CSR data) -------
__global__ __launch_bounds__(256)
void aggregate_kernel() {
    int w = (int)(((long)blockIdx.x * blockDim.x + threadIdx.x) >> 5);
    int lane = threadIdx.x & 31;
    if (w >= NN) return;
    long off = g_off[w]; int deg = g_deg[w];
    float a0 = 0.f, a1 = 0.f, a2 = 0.f, a3 = 0.f, a4 = 0.f;
    const int* sp = g_csrc + off;
    const float* ap = g_csc + off * 5;
    #pragma unroll 2
    for (int i = 0; i < deg; i++) {
        int s = sp[i];                               // broadcast
        const float* xr = g_xl + (long)s * DIM + lane;
        const float* al = ap + (long)i * 5;          // broadcast
        a0 = fmaf(al[0], xr[0],   a0);
        a1 = fmaf(al[1], xr[32],  a1);
        a2 = fmaf(al[2], xr[64],  a2);
        a3 = fmaf(al[3], xr[96],  a3);
        a4 = fmaf(al[4], xr[128], a4);
    }
    float* o = g_attn + (long)w * DIM + lane;
    o[0] = a0; o[32] = a1; o[64] = a2; o[96] = a3; o[128] = a4;
}

// ---------------- fused tail: LN1 -> MLP(160->50->160) -> LN2 ---------------
__global__ __launch_bounds__(256, 2)
void tail_kernel(const float* __restrict__ x, const float* __restrict__ bias,
                 const float* __restrict__ g1, const float* __restrict__ bt1,
                 const float* __restrict__ W1, const float* __restrict__ b1,
                 const float* __restrict__ gm, const float* __restrict__ bm,
                 const float* __restrict__ W2, const float* __restrict__ b2,
                 const float* __restrict__ g2, const float* __restrict__ bt2,
                 float* __restrict__ out) {
    extern __shared__ float sm[];
    float* W1_s  = sm;                 // 160*50
    float* W2_s  = W1_s + DIM * MH;    // 50*160
    float* hbuf  = W2_s + MH * DIM;    // 32*161
    float* tbuf  = hbuf + 32 * 161;    // 32*51
    float* bias_s = tbuf + 32 * 51;
    float* g1_s  = bias_s + DIM;
    float* bt1_s = g1_s + DIM;
    float* b2_s  = bt1_s + DIM;
    float* g2_s  = b2_s + DIM;
    float* bt2_s = g2_s + DIM;
    float* b1_s  = bt2_s + DIM;
    float* gm_s  = b1_s + MH;
    float* bm_s  = gm_s + MH;
    int tid = threadIdx.x, lane = tid & 31, warp = tid >> 5;

    for (int i = tid; i < DIM * MH; i += 256) { W1_s[i] = W1[i]; W2_s[i] = W2[i]; }
    if (tid < DIM) {
        bias_s[tid] = bias[tid]; g1_s[tid] = g1[tid]; bt1_s[tid] = bt1[tid];
        b2_s[tid] = b2[tid]; g2_s[tid] = g2[tid]; bt2_s[tid] = bt2[tid];
    }
    if (tid < MH) { b1_s[tid] = b1[tid]; gm_s[tid] = gm[tid]; bm_s[tid] = bm[tid]; }
    __syncthreads();

    for (int chunk = blockIdx.x; chunk < NCHUNK; chunk += gridDim.x) {
        int n0 = chunk * 32;
        #pragma unroll
        for (int i = 0; i < 4; i++) {
            int nl = warp + 8 * i;
            long n = n0 + nl;
            float v[5];
            if (n < NN) {
                #pragma unroll
                for (int c = 0; c < 5; c++) {
                    int col = lane + 32 * c;
                    v[c] = x[n * DIM + col] + g_attn[n * DIM + col] + bias_s[col];
                }
            } else {
                #pragma unroll
                for (int c = 0; c < 5; c++) v[c] = 0.f;
            }
            float s1 = 0.f, s2 = 0.f;
            #pragma unroll
            for (int c = 0; c < 5; c++) { s1 += v[c]; s2 += v[c] * v[c]; }
            #pragma unroll
            for (int off = 16; off; off >>= 1) {
                s1 += __shfl_xor_sync(0xffffffffu, s1, off);
                s2 += __shfl_xor_sync(0xffffffffu, s2, off);
            }
            float mu = s1 * (1.f / DIM);
            float rstd = rsqrtf(s2 * (1.f / DIM) - mu * mu + 1e-5f);
            #pragma unroll
            for (int c = 0; c < 5; c++) {
                int col = lane + 32 * c;
                hbuf[nl * 161 + col] = (v[c] - mu) * rstd * g1_s[col] + bt1_s[col];
            }
        }
        __syncthreads();
        {
            int cg = lane, ng = warp;
            float a0[4] = {0.f,0.f,0.f,0.f}, a1[4] = {0.f,0.f,0.f,0.f};
            for (int k = 0; k < DIM; k++) {
                float w0 = W1_s[k * MH + cg];
                float w1 = (cg < MH - 32) ? W1_s[k * MH + cg + 32] : 0.f;
                #pragma unroll
                for (int i = 0; i < 4; i++) {
                    float hv = hbuf[(ng * 4 + i) * 161 + k];
                    a0[i] = fmaf(hv, w0, a0[i]);
                    a1[i] = fmaf(hv, w1, a1[i]);
                }
            }
            #pragma unroll
            for (int i = 0; i < 4; i++) {
                int nl = ng * 4 + i;
                tbuf[nl * 51 + cg] = selu_f(a0[i] + b1_s[cg]);
                if (cg < MH - 32)
                    tbuf[nl * 51 + cg + 32] = selu_f(a1[i] + b1_s[cg + 32]);
            }
        }
        __syncthreads();
        if (tid < 32) {
            float s1 = 0.f, s2 = 0.f;
            for (int k = 0; k < MH; k++) { float t = tbuf[tid * 51 + k]; s1 += t; s2 += t * t; }
            float mu = s1 * (1.f / MH);
            float rstd = rsqrtf(s2 * (1.f / MH) - mu * mu + 1e-5f);
            for (int k = 0; k < MH; k++)
                tbuf[tid * 51 + k] = (tbuf[tid * 51 + k] - mu) * rstd * gm_s[k] + bm_s[k];
        }
        __syncthreads();
        {
            float acc[4][5];
            #pragma unroll
            for (int i = 0; i < 4; i++)
                #pragma unroll
                for (int c = 0; c < 5; c++) acc[i][c] = 0.f;
            for (int k = 0; k < MH; k++) {
                float wv[5];
                #pragma unroll
                for (int c = 0; c < 5; c++) wv[c] = W2_s[k * DIM + lane + 32 * c];
                #pragma unroll
                for (int i = 0; i < 4; i++) {
                    float uv = tbuf[(warp * 4 + i) * 51 + k];
                    #pragma unroll
                    for (int c = 0; c < 5; c++) acc[i][c] = fmaf(uv, wv[c], acc[i][c]);
                }
            }
            #pragma unroll
            for (int i = 0; i < 4; i++) {
                int nl = warp * 4 + i;
                long n = n0 + nl;
                float v[5];
                #pragma unroll
                for (int c = 0; c < 5; c++) {
                    int col = lane + 32 * c;
                    v[c] = hbuf[nl * 161 + col] + acc[i][c] + b2_s[col];
                }
                float s1 = 0.f, s2 = 0.f;
                #pragma unroll
                for (int c = 0; c < 5; c++) { s1 += v[c]; s2 += v[c] * v[c]; }
                #pragma unroll
                for (int off = 16; off; off >>= 1) {
                    s1 += __shfl_xor_sync(0xffffffffu, s1, off);
                    s2 += __shfl_xor_sync(0xffffffffu, s2, off);
                }
                float mu = s1 * (1.f / DIM);
                float rstd = rsqrtf(s2 * (1.f / DIM) - mu * mu + 1e-5f);
                if (n < NN) {
                    #pragma unroll
                    for (int c = 0; c < 5; c++) {
                        int col = lane + 32 * c;
                        out[n * DIM + col] = (v[c] - mu) * rstd * g2_s[col] + bt2_s[col];
                    }
                }
            }
        }
        __syncthreads();
    }
}

// ---------------- launch ----------------
extern "C" void kernel_launch(void* const* d_in, const int* in_sizes, int n_in,
                              void* d_out, int out_size) {
    const float* x         = (const float*)d_in[0];
    const int*   edge_index= (const int*)d_in[1];
    const float* edge_attr = (const float*)d_in[2];
    const float* Wl  = (const float*)d_in[5];
    const float* bl  = (const float*)d_in[6];
    const float* Wr  = (const float*)d_in[7];
    const float* br  = (const float*)d_in[8];
    const float* We  = (const float*)d_in[9];
    const float* att = (const float*)d_in[10];
    const float* bias= (const float*)d_in[11];
    const float* g1  = (const float*)d_in[12];
    const float* bt1 = (const float*)d_in[13];
    const float* W1  = (const float*)d_in[14];
    const float* b1  = (const float*)d_in[15];
    const float* gm  = (const float*)d_in[16];
    const float* bm  = (const float*)d_in[17];
    const float* W2  = (const float*)d_in[18];
    const float* b2  = (const float*)d_in[19];
    const float* g2  = (const float*)d_in[20];
    const float* bt2 = (const float*)d_in[21];
    float* out = (float*)d_out;
    const int* src = edge_index;
    const int* dst = edge_index + NE;

    const int SM_NODE = (DIM * WTS + 2 * TILE * DIM) * (int)sizeof(float);       // 226560
    const int SM_EDGE = (DIM * WTS + 2 * TILE * DIM + DIM) * (int)sizeof(float); // 227200
    const int SM_TAIL = (2 * DIM * MH + 32 * 161 + 32 * 51 + 6 * DIM + 3 * MH)
                        * (int)sizeof(float);
    cudaFuncSetAttribute(node_transform_kernel, cudaFuncAttributeMaxDynamicSharedMemorySize, SM_NODE);
    cudaFuncSetAttribute(edge_score_kernel,     cudaFuncAttributeMaxDynamicSharedMemorySize, SM_EDGE);
    cudaFuncSetAttribute(tail_kernel,           cudaFuncAttributeMaxDynamicSharedMemorySize, SM_TAIL);

    zero_deg_kernel<<<(NN + 255) / 256, 256>>>();                      // 0
    count_kernel<<<(NE + 255) / 256, 256>>>(dst);                      // 1
    scan1_kernel<<<NB, 256>>>();                                       // 2
    node_transform_kernel<<<dim3(148, 2), 512, SM_NODE>>>(x, Wl, bl, Wr, br); // 3 (profiled)
    scan2_kernel<<<1, 256>>>();                                        // 4
    scan3_kernel<<<(NN + 255) / 256, 256>>>();                         // 5
    fill_kernel<<<(NE + 255) / 256, 256>>>(src, dst);                  // 6
    edge_score_kernel<<<148, 512, SM_EDGE>>>(edge_attr, src, dst, We, att); // 7
    softmax_kernel<<<(NN + 7) / 8, 256>>>();                           // 8
    aggregate_kernel<<<(NN + 7) / 8, 256>>>();                         // 9
    tail_kernel<<<296, 256, SM_TAIL>>>(x, bias, g1, bt1, W1, b1, gm, bm,
                                       W2, b2, g2, bt2, out);          // 10
}

// round 7
// speedup vs baseline: 1.5213x; 1.0290x over previous
#include <cuda_runtime.h>
#include <cstdint>

typedef unsigned long long ull;

#define NN    50000
#define NE    500000
#define DIM   160
#define HEADS 5
#define MH    50
#define NV4   (DIM/4)      // 40 float4 per row
#define TILE  96           // rows per GEMM tile
#define RPW   6            // rows per warp (16 warps)
#define NB    ((NN + 255) / 256)   // scan blocks
#define NCHUNK ((NN + 31) / 32)

// ---------------- scratch (static device globals: allocation-free) ----------
__device__ float g_xl[NN * DIM];
__device__ float g_xr[NN * DIM];
__device__ float g_attn[NN * DIM];
__device__ float g_esc[(size_t)NE * HEADS];    // raw scores, edge order
__device__ float g_alpha[(size_t)NE * HEADS];  // exp(score-max), CSR order
__device__ int   g_csrc[NE];                   // src node per CSR slot
__device__ int   g_eid[NE];                    // CSR slot -> edge id
__device__ int   g_deg[NN];
__device__ int   g_off[NN];
__device__ int   g_cur[NN];
__device__ int   g_bsum[256];

__device__ __forceinline__ float selu_f(float v) {
    const float sc = 1.0507009873554805f, al = 1.6732632423543772f;
    return v > 0.f ? sc * v : sc * al * (expf(v) - 1.f);
}

#define FFMA2(d, a, b) asm("fma.rn.f32x2 %0, %1, %2, %0;" : "+l"(d) : "l"(a), "l"(b))

__device__ __forceinline__ float unpack_add(ull v) {
    return __uint_as_float((unsigned)v) + __uint_as_float((unsigned)(v >> 32));
}

// ---------------- CSR build ----------------
__global__ void zero_deg_kernel() {
    int i = blockIdx.x * blockDim.x + threadIdx.x;
    if (i < NN) g_deg[i] = 0;
}
__global__ void count_kernel(const int* __restrict__ dst) {
    int e = blockIdx.x * blockDim.x + threadIdx.x;
    if (e < NE) atomicAdd(&g_deg[dst[e]], 1);
}
__global__ void scan1_kernel() {
    __shared__ int wsum[8];
    int tid = threadIdx.x, lane = tid & 31, warp = tid >> 5;
    int i = blockIdx.x * 256 + tid;
    int v = (i < NN) ? g_deg[i] : 0;
    int x = v;
    #pragma unroll
    for (int d = 1; d < 32; d <<= 1) {
        int y = __shfl_up_sync(0xffffffffu, x, d);
        if (lane >= d) x += y;
    }
    if (lane == 31) wsum[warp] = x;
    __syncthreads();
    if (tid == 0) {
        int s = 0;
        #pragma unroll
        for (int j = 0; j < 8; j++) { int t = wsum[j]; wsum[j] = s; s += t; }
        g_bsum[blockIdx.x] = s;
    }
    __syncthreads();
    if (i < NN) g_off[i] = x - v + wsum[warp];
}
__global__ void scan2_kernel() {
    __shared__ int wsum[8];
    int tid = threadIdx.x, lane = tid & 31, warp = tid >> 5;
    int v = (tid < NB) ? g_bsum[tid] : 0;
    int x = v;
    #pragma unroll
    for (int d = 1; d < 32; d <<= 1) {
        int y = __shfl_up_sync(0xffffffffu, x, d);
        if (lane >= d) x += y;
    }
    if (lane == 31) wsum[warp] = x;
    __syncthreads();
    if (tid == 0) {
        int s = 0;
        #pragma unroll
        for (int j = 0; j < 8; j++) { int t = wsum[j]; wsum[j] = s; s += t; }
    }
    __syncthreads();
    if (tid < NB) g_bsum[tid] = x - v + wsum[warp];
}
__global__ void scan3_kernel() {
    int i = blockIdx.x * blockDim.x + threadIdx.x;
    if (i < NN) {
        int o = g_off[i] + g_bsum[i >> 8];
        g_off[i] = o;
        g_cur[i] = o;
    }
}
__global__ void fill_kernel(const int* __restrict__ src, const int* __restrict__ dst) {
    int e = blockIdx.x * blockDim.x + threadIdx.x;
    if (e < NE) {
        int pos = atomicAdd(&g_cur[dst[e]], 1);
        g_eid[pos] = e;
        g_csrc[pos] = src[e];
    }
}

// ---------------- cp.async tile loader: 96 rows x 160 floats ----------------
__device__ __forceinline__ void tile_load_async(float* buf, const float* src_mat,
                                                long row0, long nrows, int tid) {
    unsigned base = (unsigned)__cvta_generic_to_shared(buf);
    #pragma unroll
    for (int it = 0; it < 8; it++) {
        int i = tid + it * 512;                // 3840 float4 total
        if (i < TILE * NV4) {
            int r = i / NV4;
            long row = row0 + r;
            const float4* p = (const float4*)src_mat +
                              (row < nrows ? row * NV4 + (i - r * NV4) : 0);
            int sz = (row < nrows) ? 16 : 0;
            asm volatile("cp.async.cg.shared.global [%0], [%1], 16, %2;\n"
                         :: "r"(base + (unsigned)i * 16u), "l"(p), "r"(sz));
        }
    }
}

// ---- f32x2 GEMM mainloop: 96 rows x 160 cols, K=160, k-step 4, LDS.128 ----
// Wt4 layout: float4 entry per (k/4, col): index (k>>2)*DIM + col.
// acc[r][c] packs {even-k sum, odd-k sum}; final = lo + hi.
__device__ __forceinline__ void gemm_tile_f2(const float* __restrict__ Wt4,
                                             const float* __restrict__ a_s,
                                             int warp, int lane, ull acc[RPW][5]) {
    #pragma unroll
    for (int r = 0; r < RPW; r++)
        #pragma unroll
        for (int c = 0; c < 5; c++) acc[r][c] = 0ull;
    const float* arow = a_s + warp * RPW * DIM;
    const ulonglong2* wq = (const ulonglong2*)Wt4;
    #pragma unroll 2
    for (int k = 0; k < DIM; k += 4) {
        ulonglong2 xv[RPW];
        #pragma unroll
        for (int r = 0; r < RPW; r++)
            xv[r] = *(const ulonglong2*)(arow + r * DIM + k);   // broadcast LDS.128
        ulonglong2 wv[5];
        int base = (k >> 2) * DIM + lane;
        #pragma unroll
        for (int c = 0; c < 5; c++)
            wv[c] = wq[base + 32 * c];                           // coalesced LDS.128
        #pragma unroll
        for (int r = 0; r < RPW; r++)
            #pragma unroll
            for (int c = 0; c < 5; c++) {
                FFMA2(acc[r][c], xv[r].x, wv[c].x);
                FFMA2(acc[r][c], xv[r].y, wv[c].y);
            }
    }
}

// load W [k][col] row-major -> Wt4 [(k/4)][col][4] packed layout
__device__ __forceinline__ void load_W_t4(float* Wt4, const float* W, int tid, int nthr) {
    for (int i = tid; i < DIM * DIM; i += nthr) {
        int kk = i / DIM, cc = i - kk * DIM;
        Wt4[(((kk >> 2) * DIM) + cc) * 4 + (kk & 3)] = W[i];
    }
}

// ---------------- K: xl = x@Wl+bl, xr = x@Wr+br (grid.y selects) ------------
__global__ __launch_bounds__(512, 1)
void node_transform_kernel(const float* __restrict__ x,
                           const float* __restrict__ Wl, const float* __restrict__ bl,
                           const float* __restrict__ Wr, const float* __restrict__ br) {
    extern __shared__ float sm[];
    float* Wt4  = sm;                   // 160*160 floats (float4-packed)
    float* buf0 = sm + DIM * DIM;       // 96*160
    float* buf1 = buf0 + TILE * DIM;    // 96*160
    const float* W    = blockIdx.y ? Wr : Wl;
    const float* bias = blockIdx.y ? br : bl;
    float* out        = blockIdx.y ? g_xr : g_xl;
    int tid = threadIdx.x, lane = tid & 31, warp = tid >> 5;

    load_W_t4(Wt4, W, tid, 512);
    float bv[5];
    #pragma unroll
    for (int c = 0; c < 5; c++) bv[c] = bias[lane + 32 * c];

    int ntiles = (NN + TILE - 1) / TILE;
    float* cur = buf0; float* nxt = buf1;
    tile_load_async(cur, x, (long)blockIdx.x * TILE, NN, tid);
    asm volatile("cp.async.commit_group;\n");
    for (int t = blockIdx.x; t < ntiles; t += gridDim.x) {
        tile_load_async(nxt, x, (long)(t + gridDim.x) * TILE, NN, tid);
        asm volatile("cp.async.commit_group;\n");
        asm volatile("cp.async.wait_group 1;\n");
        __syncthreads();
        ull acc[RPW][5];
        gemm_tile_f2(Wt4, cur, warp, lane, acc);
        long r0 = (long)t * TILE + warp * RPW;
        #pragma unroll
        for (int r = 0; r < RPW; r++) {
            long gr = r0 + r;
            if (gr < NN) {
                #pragma unroll
                for (int c = 0; c < 5; c++)
                    out[gr * DIM + lane + 32 * c] = unpack_add(acc[r][c]) + bv[c];
            }
        }
        __syncthreads();
        float* tmp = cur; cur = nxt; nxt = tmp;
    }
}

// ------- K: ea = edge_attr@We, fused gather + score (edge-order out) --------
__global__ __launch_bounds__(512, 1)
void edge_score_kernel(const float* __restrict__ edge_attr,
                       const int* __restrict__ src, const int* __restrict__ dst,
                       const float* __restrict__ We, const float* __restrict__ att) {
    extern __shared__ float sm[];
    float* Wt4   = sm;
    float* buf0  = sm + DIM * DIM;
    float* buf1  = buf0 + TILE * DIM;
    float* att_s = buf1 + TILE * DIM;
    int tid = threadIdx.x, lane = tid & 31, warp = tid >> 5;

    load_W_t4(Wt4, We, tid, 512);
    if (tid < DIM) att_s[tid] = att[tid];

    int ntiles = (NE + TILE - 1) / TILE;
    float* cur = buf0; float* nxt = buf1;
    tile_load_async(cur, edge_attr, (long)blockIdx.x * TILE, NE, tid);
    asm volatile("cp.async.commit_group;\n");
    for (int t = blockIdx.x; t < ntiles; t += gridDim.x) {
        tile_load_async(nxt, edge_attr, (long)(t + gridDim.x) * TILE, NE, tid);
        asm volatile("cp.async.commit_group;\n");
        asm volatile("cp.async.wait_group 1;\n");
        __syncthreads();
        ull acc[RPW][5];
        gemm_tile_f2(Wt4, cur, warp, lane, acc);
        int e0 = t * TILE + warp * RPW;
        #pragma unroll
        for (int r = 0; r < RPW; r++) {
            int e = e0 + r;
            if (e < NE) {                      // uniform across warp
                int s = src[e], d = dst[e];
                const float* xlr = g_xl + (long)s * DIM;
                const float* xrr = g_xr + (long)d * DIM;
                #pragma unroll
                for (int c = 0; c < 5; c++) {  // c == head, lane == channel
                    int col = lane + 32 * c;
                    float m = unpack_add(acc[r][c]) + xlr[col] + xrr[col];
                    m = (m > 0.f) ? m : 0.2f * m;         // leaky_relu 0.2
                    float v = m * att_s[col];
                    #pragma unroll
                    for (int off = 16; off; off >>= 1)
                        v += __shfl_xor_sync(0xffffffffu, v, off);
                    if (lane == 0)
                        g_esc[(long)e * HEADS + c] = v;   // raw score, edge order
                }
            }
        }
        __syncthreads();
        float* tmp = cur; cur = nxt; nxt = tmp;
    }
}

// ------ fused softmax + aggregate (warp per node, CSR; no atomics) ----------
__global__ __launch_bounds__(256)
void softagg_kernel() {
    int w = (int)(((long)blockIdx.x * blockDim.x + threadIdx.x) >> 5);
    int lane = threadIdx.x & 31;
    if (w >= NN) return;
    long off = g_off[w]; int deg = g_deg[w];
    // pass 1: per-head max (gather scores via eid)
    float mx[5];
    #pragma unroll
    for (int h = 0; h < 5; h++) mx[h] = -3.4e38f;
    for (int i = lane; i < deg; i += 32) {
        long e = g_eid[off + i];
        const float* p = g_esc + e * 5;
        #pragma unroll
        for (int h = 0; h < 5; h++) mx[h] = fmaxf(mx[h], p[h]);
    }
    #pragma unroll
    for (int h = 0; h < 5; h++)
        #pragma unroll
        for (int o = 16; o; o >>= 1)
            mx[h] = fmaxf(mx[h], __shfl_xor_sync(0xffffffffu, mx[h], o));
    // pass 2: exp + sum, write exps to CSR-ordered g_alpha
    float sm[5] = {0.f, 0.f, 0.f, 0.f, 0.f};
    for (int i = lane; i < deg; i += 32) {
        long e = g_eid[off + i];
        const float* p = g_esc + e * 5;
        float* q = g_alpha + (off + i) * 5;
        #pragma unroll
        for (int h = 0; h < 5; h++) {
            float v = expf(p[h] - mx[h]);
            q[h] = v;
            sm[h] += v;
        }
    }
    #pragma unroll
    for (int h = 0; h < 5; h++)
        #pragma unroll
        for (int o = 16; o; o >>= 1)
            sm[h] += __shfl_xor_sync(0xffffffffu, sm[h], o);
    float inv[5];
    #pragma unroll
    for (int h = 0; h < 5; h++) inv[h] = (deg > 0) ? 1.f / sm[h] : 0.f;
    // pass 3: aggregate raw exps (serial broadcast over edges), scale at end
    float a0 = 0.f, a1 = 0.f, a2 = 0.f, a3 = 0.f, a4 = 0.f;
    const int* sp = g_csrc + off;
    const float* ap = g_alpha + off * 5;
    #pragma unroll 2
    for (int i = 0; i < deg; i++) {
        int s = sp[i];                               // broadcast
        const float* xr = g_xl + (long)s * DIM + lane;
        const float* al = ap + (long)i * 5;          // broadcast
        a0 = fmaf(al[0], xr[0],   a0);
        a1 = fmaf(al[1], xr[32],  a1);
        a2 = fmaf(al[2], xr[64],  a2);
        a3 = fmaf(al[3], xr[96],  a3);
        a4 = fmaf(al[4], xr[128], a4);
    }
    float* o = g_attn + (long)w * DIM + lane;
    o[0] = a0 * inv[0]; o[32] = a1 * inv[1]; o[64] = a2 * inv[2];
    o[96] = a3 * inv[3]; o[128] = a4 * inv[4];
}

// ---------------- fused tail: LN1 -> MLP(160->50->160) -> LN2 ---------------
__global__ __launch_bounds__(256, 2)
void tail_kernel(const float* __restrict__ x, const float* __restrict__ bias,
                 const float* __restrict__ g1, const float* __restrict__ bt1,
                 const float* __restrict__ W1, const float* __restrict__ b1,
                 const float* __restrict__ gm, const float* __restrict__ bm,
                 const float* __restrict__ W2, const float* __restrict__ b2,
                 const float* __restrict__ g2, const float* __restrict__ bt2,
                 float* __restrict__ out) {
    extern __shared__ float sm[];
    float* W1_s  = sm;                 // 160*50
    float* W2_s  = W1_s + DIM * MH;    // 50*160
    float* hbuf  = W2_s + MH * DIM;    // 32*161
    float* tbuf  = hbuf + 32 * 161;    // 32*51
    float* bias_s = tbuf + 32 * 51;
    float* g1_s  = bias_s + DIM;
    float* bt1_s = g1_s + DIM;
    float* b2_s  = bt1_s + DIM;
    float* g2_s  = b2_s + DIM;
    float* bt2_s = g2_s + DIM;
    float* b1_s  = bt2_s + DIM;
    float* gm_s  = b1_s + MH;
    float* bm_s  = gm_s + MH;
    int tid = threadIdx.x, lane = tid & 31, warp = tid >> 5;

    for (int i = tid; i < DIM * MH; i += 256) { W1_s[i] = W1[i]; W2_s[i] = W2[i]; }
    if (tid < DIM) {
        bias_s[tid] = bias[tid]; g1_s[tid] = g1[tid]; bt1_s[tid] = bt1[tid];
        b2_s[tid] = b2[tid]; g2_s[tid] = g2[tid]; bt2_s[tid] = bt2[tid];
    }
    if (tid < MH) { b1_s[tid] = b1[tid]; gm_s[tid] = gm[tid]; bm_s[tid] = bm[tid]; }
    __syncthreads();

    for (int chunk = blockIdx.x; chunk < NCHUNK; chunk += gridDim.x) {
        int n0 = chunk * 32;
        #pragma unroll
        for (int i = 0; i < 4; i++) {
            int nl = warp + 8 * i;
            long n = n0 + nl;
            float v[5];
            if (n < NN) {
                #pragma unroll
                for (int c = 0; c < 5; c++) {
                    int col = lane + 32 * c;
                    v[c] = x[n * DIM + col] + g_attn[n * DIM + col] + bias_s[col];
                }
            } else {
                #pragma unroll
                for (int c = 0; c < 5; c++) v[c] = 0.f;
            }
            float s1 = 0.f, s2 = 0.f;
            #pragma unroll
            for (int c = 0; c < 5; c++) { s1 += v[c]; s2 += v[c] * v[c]; }
            #pragma unroll
            for (int off = 16; off; off >>= 1) {
                s1 += __shfl_xor_sync(0xffffffffu, s1, off);
                s2 += __shfl_xor_sync(0xffffffffu, s2, off);
            }
            float mu = s1 * (1.f / DIM);
            float rstd = rsqrtf(s2 * (1.f / DIM) - mu * mu + 1e-5f);
            #pragma unroll
            for (int c = 0; c < 5; c++) {
                int col = lane + 32 * c;
                hbuf[nl * 161 + col] = (v[c] - mu) * rstd * g1_s[col] + bt1_s[col];
            }
        }
        __syncthreads();
        {
            int cg = lane, ng = warp;
            float a0[4] = {0.f,0.f,0.f,0.f}, a1[4] = {0.f,0.f,0.f,0.f};
            for (int k = 0; k < DIM; k++) {
                float w0 = W1_s[k * MH + cg];
                float w1 = (cg < MH - 32) ? W1_s[k * MH + cg + 32] : 0.f;
                #pragma unroll
                for (int i = 0; i < 4; i++) {
                    float hv = hbuf[(ng * 4 + i) * 161 + k];
                    a0[i] = fmaf(hv, w0, a0[i]);
                    a1[i] = fmaf(hv, w1, a1[i]);
                }
            }
            #pragma unroll
            for (int i = 0; i < 4; i++) {
                int nl = ng * 4 + i;
                tbuf[nl * 51 + cg] = selu_f(a0[i] + b1_s[cg]);
                if (cg < MH - 32)
                    tbuf[nl * 51 + cg + 32] = selu_f(a1[i] + b1_s[cg + 32]);
            }
        }
        __syncthreads();
        if (tid < 32) {
            float s1 = 0.f, s2 = 0.f;
            for (int k = 0; k < MH; k++) { float t = tbuf[tid * 51 + k]; s1 += t; s2 += t * t; }
            float mu = s1 * (1.f / MH);
            float rstd = rsqrtf(s2 * (1.f / MH) - mu * mu + 1e-5f);
            for (int k = 0; k < MH; k++)
                tbuf[tid * 51 + k] = (tbuf[tid * 51 + k] - mu) * rstd * gm_s[k] + bm_s[k];
        }
        __syncthreads();
        {
            float acc[4][5];
            #pragma unroll
            for (int i = 0; i < 4; i++)
                #pragma unroll
                for (int c = 0; c < 5; c++) acc[i][c] = 0.f;
            for (int k = 0; k < MH; k++) {
                float wv[5];
                #pragma unroll
                for (int c = 0; c < 5; c++) wv[c] = W2_s[k * DIM + lane + 32 * c];
                #pragma unroll
                for (int i = 0; i < 4; i++) {
                    float uv = tbuf[(warp * 4 + i) * 51 + k];
                    #pragma unroll
                    for (int c = 0; c < 5; c++) acc[i][c] = fmaf(uv, wv[c], acc[i][c]);
                }
            }
            #pragma unroll
            for (int i = 0; i < 4; i++) {
                int nl = warp * 4 + i;
                long n = n0 + nl;
                float v[5];
                #pragma unroll
                for (int c = 0; c < 5; c++) {
                    int col = lane + 32 * c;
                    v[c] = hbuf[nl * 161 + col] + acc[i][c] + b2_s[col];
                }
                float s1 = 0.f, s2 = 0.f;
                #pragma unroll
                for (int c = 0; c < 5; c++) { s1 += v[c]; s2 += v[c] * v[c]; }
                #pragma unroll
                for (int off = 16; off; off >>= 1) {
                    s1 += __shfl_xor_sync(0xffffffffu, s1, off);
                    s2 += __shfl_xor_sync(0xffffffffu, s2, off);
                }
                float mu = s1 * (1.f / DIM);
                float rstd = rsqrtf(s2 * (1.f / DIM) - mu * mu + 1e-5f);
                if (n < NN) {
                    #pragma unroll
                    for (int c = 0; c < 5; c++) {
                        int col = lane + 32 * c;
                        out[n * DIM + col] = (v[c] - mu) * rstd * g2_s[col] + bt2_s[col];
                    }
                }
            }
        }
        __syncthreads();
    }
}

// ---------------- launch ----------------
extern "C" void kernel_launch(void* const* d_in, const int* in_sizes, int n_in,
                              void* d_out, int out_size) {
    const float* x         = (const float*)d_in[0];
    const int*   edge_index= (const int*)d_in[1];
    const float* edge_attr = (const float*)d_in[2];
    const float* Wl  = (const float*)d_in[5];
    const float* bl  = (const float*)d_in[6];
    const float* Wr  = (const float*)d_in[7];
    const float* br  = (const float*)d_in[8];
    const float* We  = (const float*)d_in[9];
    const float* att = (const float*)d_in[10];
    const float* bias= (const float*)d_in[11];
    const float* g1  = (const float*)d_in[12];
    const float* bt1 = (const float*)d_in[13];
    const float* W1  = (const float*)d_in[14];
    const float* b1  = (const float*)d_in[15];
    const float* gm  = (const float*)d_in[16];
    const float* bm  = (const float*)d_in[17];
    const float* W2  = (const float*)d_in[18];
    const float* b2  = (const float*)d_in[19];
    const float* g2  = (const float*)d_in[20];
    const float* bt2 = (const float*)d_in[21];
    float* out = (float*)d_out;
    const int* src = edge_index;
    const int* dst = edge_index + NE;

    const int SM_NODE = (DIM * DIM + 2 * TILE * DIM) * (int)sizeof(float);       // 225280
    const int SM_EDGE = (DIM * DIM + 2 * TILE * DIM + DIM) * (int)sizeof(float); // 225920
    const int SM_TAIL = (2 * DIM * MH + 32 * 161 + 32 * 51 + 6 * DIM + 3 * MH)
                        * (int)sizeof(float);
    cudaFuncSetAttribute(node_transform_kernel, cudaFuncAttributeMaxDynamicSharedMemorySize, SM_NODE);
    cudaFuncSetAttribute(edge_score_kernel,     cudaFuncAttributeMaxDynamicSharedMemorySize, SM_EDGE);
    cudaFuncSetAttribute(tail_kernel,           cudaFuncAttributeMaxDynamicSharedMemorySize, SM_TAIL);

    node_transform_kernel<<<dim3(148, 2), 512, SM_NODE>>>(x, Wl, bl, Wr, br); // 0
    zero_deg_kernel<<<(NN + 255) / 256, 256>>>();                             // 1
    count_kernel<<<(NE + 255) / 256, 256>>>(dst);                             // 2
    edge_score_kernel<<<148, 512, SM_EDGE>>>(edge_attr, src, dst, We, att);   // 3 (profiled)
    scan1_kernel<<<NB, 256>>>();                                              // 4
    scan2_kernel<<<1, 256>>>();                                               // 5
    scan3_kernel<<<(NN + 255) / 256, 256>>>();                                // 6
    fill_kernel<<<(NE + 255) / 256, 256>>>(src, dst);                         // 7
    softagg_kernel<<<(NN + 7) / 8, 256>>>();                                  // 8
    tail_kernel<<<296, 256, SM_TAIL>>>(x, bias, g1, bt1, W1, b1, gm, bm,
                                       W2, b2, g2, bt2, out);                 // 9
}